// round 1
// baseline (speedup 1.0000x reference)
#include <cuda_runtime.h>

#define Hh 256
#define Ww 256
#define Pp 65536
#define Fn 640
#define Vn 322
#define EPSf 1e-8f
#define BIGf 1e10f
#define FOCALf 3.73205080756887729f
#define NBLK 256

// -------- device-global scratch (no allocations allowed) --------
__device__ float4 g_A[Fn];                 // P0x, P0y, P0c, P1x
__device__ float4 g_B[Fn];                 // P1y, P1c, D0,  D1
__device__ float  g_D2[Fn];                // D2
__device__ float  g_tex[Fn * 64 * 3];      // tanh(textures)
__device__ double g_partial[NBLK];

// ---------------- kernel 1: vertex transform + face coefficients ----------------
__global__ void prep_kernel(const float* __restrict__ verts,
                            const int*   __restrict__ faces,
                            const float* __restrict__ angle) {
    __shared__ float sx[Vn], sy[Vn], sd[Vn];
    int t = threadIdx.x;
    float th = angle[0] * 6.28318530717958647692f;
    float c = cosf(th), s = sinf(th);
    if (t < Vn) {
        float x = verts[3 * t], y = verts[3 * t + 1], z = verts[3 * t + 2];
        float xr = c * x + s * z;
        float zr = -s * x + c * z;
        float depth = 2.732f - zr;
        sx[t] = FOCALf * xr / depth;
        sy[t] = FOCALf * y / depth;
        sd[t] = depth;
    }
    __syncthreads();
    if (t < Fn) {
        int i0 = faces[3 * t], i1 = faces[3 * t + 1], i2 = faces[3 * t + 2];
        float ax = sx[i0], ay = sy[i0];
        float bx = sx[i1], by = sy[i1];
        float cx = sx[i2], cy = sy[i2];
        float area = (bx - ax) * (cy - ay) - (by - ay) * (cx - ax);
        bool valid = fabsf(area) > EPSf;           // NaN area -> invalid (matches jnp)
        float denom = valid ? area : 1.0f;
        // w0 = edge(bx,by,cx,cy) = ((cx-bx)*(py-by) - (cy-by)*(px-bx)) / denom
        float e0x = cx - bx, e0y = cy - by;
        float4 A, B;
        A.x = -e0y / denom;                        // * px
        A.y =  e0x / denom;                        // * py
        A.z = (e0y * bx - e0x * by) / denom;       // const
        // w1 = edge(cx,cy,ax,ay)
        float e1x = ax - cx, e1y = ay - cy;
        A.w = -e1y / denom;
        B.x =  e1x / denom;
        B.y = (e1y * cx - e1x * cy) / denom;
        B.z = sd[i0];
        B.w = sd[i1];
        float D2 = sd[i2];
        if (!valid) {                              // sentinel: w0 == -1e30 -> never inside
            A.x = 0.f; A.y = 0.f; A.z = -1e30f;
            A.w = 0.f; B.x = 0.f; B.y = 0.f;
        }
        g_A[t] = A; g_B[t] = B; g_D2[t] = D2;
    }
}

// ---------------- kernel 2: tanh of textures ----------------
__global__ void tanh_kernel(const float* __restrict__ tex) {
    int i = blockIdx.x * blockDim.x + threadIdx.x;
    if (i < Fn * 64 * 3) g_tex[i] = tanhf(tex[i]);
}

// ---------------- kernel 3: rasterize + shade + per-block partial loss ----------------
__global__ void __launch_bounds__(256) raster_kernel(const float* __restrict__ ref) {
    __shared__ float4 sA[Fn];
    __shared__ float4 sB[Fn];
    __shared__ float  sD2[Fn];
    int tid = threadIdx.x;
    for (int i = tid; i < Fn; i += blockDim.x) {
        sA[i] = g_A[i]; sB[i] = g_B[i]; sD2[i] = g_D2[i];
    }
    __syncthreads();

    int p = blockIdx.x * blockDim.x + tid;         // 256 blocks * 256 thr = 65536 pixels
    int w = p & (Ww - 1);
    int h = p >> 8;
    float px = (w + 0.5f) / 256.0f * 2.0f - 1.0f;  // exact (power-of-2 divides)
    float py = 1.0f - (h + 0.5f) / 256.0f * 2.0f;

    float best = BIGf;
    int   bi = 0;
    float bw0 = 0.f, bw1 = 0.f;

#pragma unroll 4
    for (int f = 0; f < Fn; f++) {
        float4 A  = sA[f];
        float4 Bv = sB[f];
        float  D2 = sD2[f];
        float w0 = fmaf(A.x, px, fmaf(A.y, py, A.z));
        float w1 = fmaf(A.w, px, fmaf(Bv.x, py, Bv.y));
        float w2 = 1.0f - w0 - w1;
        float z  = fmaf(w0, Bv.z, fmaf(w1, Bv.w, w2 * D2));
        // strict < with ascending f == jnp.argmin first-min tie-break
        bool take = (w0 >= 0.f) & (w1 >= 0.f) & (w2 >= 0.f) & (z > EPSf) & (z < best);
        if (take) { best = z; bi = f; bw0 = w0; bw1 = w1; }
    }

    float col0 = 0.f, col1 = 0.f, col2 = 0.f;
    if (best < 0.5f * BIGf) {
        float pw[3] = { bw0, bw1, 1.0f - bw0 - bw1 };
        int   i0[3];
        float fr[3];
#pragma unroll
        for (int k = 0; k < 3; k++) {
            float u  = fminf(fmaxf(pw[k], 0.f), 1.f) * 3.0f;   // *(TS-1)
            float fl = floorf(u);
            fl = fminf(fmaxf(fl, 0.f), 2.f);                   // clip to TS-2
            i0[k] = (int)fl;
            fr[k] = u - fl;
        }
        const float* tb = g_tex + bi * 192;
#pragma unroll
        for (int a = 0; a < 2; a++)
#pragma unroll
            for (int b = 0; b < 2; b++)
#pragma unroll
                for (int cc = 0; cc < 2; cc++) {
                    float wc = (a ? fr[0] : 1.f - fr[0])
                             * (b ? fr[1] : 1.f - fr[1])
                             * (cc ? fr[2] : 1.f - fr[2]);
                    int idx = ((i0[0] + a) * 16 + (i0[1] + b) * 4 + (i0[2] + cc)) * 3;
                    col0 += wc * tb[idx + 0];
                    col1 += wc * tb[idx + 1];
                    col2 += wc * tb[idx + 2];
                }
    }

    float d0 = col0 - ref[p];
    float d1 = col1 - ref[Pp + p];
    float d2 = col2 - ref[2 * Pp + p];
    double sum = (double)d0 * d0 + (double)d1 * d1 + (double)d2 * d2;

    // deterministic in-block reduction (no float atomics)
#pragma unroll
    for (int o = 16; o; o >>= 1) sum += __shfl_down_sync(0xffffffffu, sum, o);
    __shared__ double ss[8];
    int lane = tid & 31, wid = tid >> 5;
    if (lane == 0) ss[wid] = sum;
    __syncthreads();
    if (tid == 0) {
        double tsum = 0.0;
        for (int i = 0; i < 8; i++) tsum += ss[i];
        g_partial[blockIdx.x] = tsum;
    }
}

// ---------------- kernel 4: deterministic final reduction ----------------
__global__ void reduce_kernel(float* out) {
    __shared__ double s[NBLK];
    int t = threadIdx.x;
    s[t] = g_partial[t];
    __syncthreads();
    for (int o = NBLK / 2; o; o >>= 1) {
        if (t < o) s[t] += s[t + o];
        __syncthreads();
    }
    if (t == 0) out[0] = (float)s[0];
}

extern "C" void kernel_launch(void* const* d_in, const int* in_sizes, int n_in,
                              void* d_out, int out_size) {
    const float* verts  = (const float*)d_in[0];   // (1,322,3)
    const int*   faces  = (const int*)  d_in[1];   // (1,640,3)
    const float* tex    = (const float*)d_in[2];   // (1,640,4,4,4,3)
    const float* ref    = (const float*)d_in[3];   // (1,3,256,256)
    const float* angle  = (const float*)d_in[4];   // (1,)

    prep_kernel<<<1, Fn>>>(verts, faces, angle);
    tanh_kernel<<<(Fn * 192 + 255) / 256, 256>>>(tex);
    raster_kernel<<<NBLK, 256>>>(ref);
    reduce_kernel<<<1, NBLK>>>((float*)d_out);
}

// round 2
// speedup vs baseline: 1.9267x; 1.9267x over previous
#include <cuda_runtime.h>

#define Fn 640
#define Vn 322
#define EPSf 1e-8f
#define HALF_BIGf 5e9f
#define FOCALf 3.73205080756887729f
#define NTILE 256            // 16x16 tiles of 16x16 pixels
#define TANH_BLOCKS 480      // 480*256 = 122880 = 640*4*4*4*3 exactly
#define BIN_BLOCKS 32        // 8 tiles per block (warp per tile)

// -------- device-global scratch (no allocations allowed) --------
__device__ float4 g_F0[Fn];                 // w0x w0y w0c w1x
__device__ float4 g_F1[Fn];                 // w1y w1c w2x w2y
__device__ float4 g_F2[Fn];                 // w2c zx  zy  zc
__device__ float  g_tex[Fn * 192];          // tanh(textures)
__device__ unsigned short g_list[NTILE * Fn];
__device__ int    g_cnt[NTILE];
__device__ double g_partial[NTILE];
__device__ unsigned int g_rcount;

// ============ K1: tanh (blocks 0..479) + prep&bin (blocks 480..511) ============
__global__ void __launch_bounds__(256) k1_kernel(const float* __restrict__ verts,
                                                 const int*   __restrict__ faces,
                                                 const float* __restrict__ angle,
                                                 const float* __restrict__ tex) {
    int b = blockIdx.x, tid = threadIdx.x;
    if (b < TANH_BLOCKS) {
        int i = b * 256 + tid;
        g_tex[i] = tanhf(tex[i]);
        return;
    }
    // ---- prep (redundant per bin block; cheap) ----
    __shared__ float sx[Vn], sy[Vn], sd[Vn];
    __shared__ float4 sF0[Fn], sF1[Fn], sF2[Fn];
    float th = angle[0] * 6.28318530717958647692f;
    float c = cosf(th), s = sinf(th);
    for (int v = tid; v < Vn; v += 256) {
        float x = verts[3 * v], y = verts[3 * v + 1], z = verts[3 * v + 2];
        float xr = c * x + s * z;
        float zr = -s * x + c * z;
        float depth = 2.732f - zr;
        sx[v] = FOCALf * xr / depth;
        sy[v] = FOCALf * y / depth;
        sd[v] = depth;
    }
    __syncthreads();
    bool writer = (b == TANH_BLOCKS);
    for (int f = tid; f < Fn; f += 256) {
        int i0 = faces[3 * f], i1 = faces[3 * f + 1], i2 = faces[3 * f + 2];
        float ax = sx[i0], ay = sy[i0];
        float bx = sx[i1], by = sy[i1];
        float cx = sx[i2], cy = sy[i2];
        float area = (bx - ax) * (cy - ay) - (by - ay) * (cx - ax);
        bool valid = fabsf(area) > EPSf;            // NaN -> invalid, matches jnp
        float denom = valid ? area : 1.0f;
        float e0x = cx - bx, e0y = cy - by;
        float w0x = -e0y / denom, w0y = e0x / denom, w0c = (e0y * bx - e0x * by) / denom;
        float e1x = ax - cx, e1y = ay - cy;
        float w1x = -e1y / denom, w1y = e1x / denom, w1c = (e1y * cx - e1x * cy) / denom;
        if (!valid) { w0x = 0.f; w0y = 0.f; w0c = -1e30f; w1x = 0.f; w1y = 0.f; w1c = 0.f; }
        float w2x = -(w0x + w1x), w2y = -(w0y + w1y), w2c = 1.0f - w0c - w1c;
        float d0 = sd[i0], d1 = sd[i1], d2 = sd[i2];
        float e02 = d0 - d2, e12 = d1 - d2;
        float zx = w0x * e02 + w1x * e12;
        float zy = w0y * e02 + w1y * e12;
        float zc = d2 + w0c * e02 + w1c * e12;
        float4 F0 = make_float4(w0x, w0y, w0c, w1x);
        float4 F1 = make_float4(w1y, w1c, w2x, w2y);
        float4 F2 = make_float4(w2c, zx, zy, zc);
        sF0[f] = F0; sF1[f] = F1; sF2[f] = F2;
        if (writer) { g_F0[f] = F0; g_F1[f] = F1; g_F2[f] = F2; }
    }
    if (writer && tid == 0) g_rcount = 0u;
    __syncthreads();

    // ---- binning: warp per tile, dilated-edge conservative cull ----
    int wid = tid >> 5, lane = tid & 31;
    int tile = (b - TANH_BLOCKS) * 8 + wid;
    int tx = tile & 15, ty = tile >> 4;
    float cxt = (float)(tx * 16 + 8) / 128.0f - 1.0f;   // tile-center pixel coord (exact)
    float cyt = 1.0f - (float)(ty * 16 + 8) / 128.0f;
    const float hext = 7.5f / 128.0f;                    // half-extent of pixel centers
    int cnt = 0;
    for (int base = 0; base < Fn; base += 32) {
        int f = base + lane;
        float4 F0 = sF0[f];
        float4 F1 = sF1[f];
        float4 F2 = sF2[f];
        float v0 = fmaf(F0.x, cxt, fmaf(F0.y, cyt, F0.z));
        float m0 = (fabsf(F0.x) + fabsf(F0.y)) * hext
                 + 1e-5f * (fabsf(F0.x) + fabsf(F0.y) + fabsf(F0.z));
        float v1 = fmaf(F0.w, cxt, fmaf(F1.x, cyt, F1.y));
        float m1 = (fabsf(F0.w) + fabsf(F1.x)) * hext
                 + 1e-5f * (fabsf(F0.w) + fabsf(F1.x) + fabsf(F1.y));
        float v2 = fmaf(F1.z, cxt, fmaf(F1.w, cyt, F2.x));
        float m2 = (fabsf(F1.z) + fabsf(F1.w)) * hext
                 + 1e-5f * (fabsf(F1.z) + fabsf(F1.w) + fabsf(F2.x));
        bool pass = (v0 + m0 >= 0.f) & (v1 + m1 >= 0.f) & (v2 + m2 >= 0.f);
        unsigned mask = __ballot_sync(0xffffffffu, pass);
        if (pass) {
            int off = cnt + __popc(mask & ((1u << lane) - 1u));
            g_list[tile * Fn + off] = (unsigned short)f;
        }
        cnt += __popc(mask);
    }
    if (lane == 0) g_cnt[tile] = cnt;
}

// ============ K2: raster + shade + fused deterministic reduction ============
__global__ void __launch_bounds__(256) k2_kernel(const float* __restrict__ ref,
                                                 float* __restrict__ out) {
    __shared__ float4 sF0[Fn], sF1[Fn], sF2[Fn];
    __shared__ unsigned short slist[Fn];
    __shared__ double ss[8];
    __shared__ double sred[NTILE];
    __shared__ int sflag;
    int b = blockIdx.x, tid = threadIdx.x;

    int cnt = g_cnt[b];
    for (int j = tid; j < cnt; j += 256) {
        int f = g_list[b * Fn + j];
        slist[j] = (unsigned short)f;
        sF0[j] = g_F0[f];
        sF1[j] = g_F1[f];
        sF2[j] = g_F2[f];
    }
    __syncthreads();

    int x = (b & 15) * 16 + (tid & 15);
    int y = (b >> 4) * 16 + (tid >> 4);
    float px = (x + 0.5f) / 128.0f - 1.0f;   // exact, identical to reference grid
    float py = 1.0f - (y + 0.5f) / 128.0f;

    float best = HALF_BIGf;                  // == reference hit threshold
    int jw = -1;
#pragma unroll 4
    for (int j = 0; j < cnt; j++) {
        float4 F0 = sF0[j];
        float4 F1 = sF1[j];
        float4 F2 = sF2[j];
        float w0 = fmaf(F0.x, px, fmaf(F0.y, py, F0.z));
        float w1 = fmaf(F0.w, px, fmaf(F1.x, py, F1.y));
        float w2 = fmaf(F1.z, px, fmaf(F1.w, py, F2.x));
        float z  = fmaf(F2.y, px, fmaf(F2.z, py, F2.w));
        bool take = (w0 >= 0.f) & (w1 >= 0.f) & (w2 >= 0.f) & (z > EPSf) & (z < best);
        if (take) { best = z; jw = j; }      // ascending j == ascending f -> argmin tie-break
    }

    float col0 = 0.f, col1 = 0.f, col2 = 0.f;
    if (jw >= 0) {
        float4 F0 = sF0[jw];
        float4 F1 = sF1[jw];
        float w0 = fmaf(F0.x, px, fmaf(F0.y, py, F0.z));
        float w1 = fmaf(F0.w, px, fmaf(F1.x, py, F1.y));
        float pw[3] = { w0, w1, 1.0f - w0 - w1 };
        int   i0[3];
        float fr[3];
#pragma unroll
        for (int k = 0; k < 3; k++) {
            float u  = fminf(fmaxf(pw[k], 0.f), 1.f) * 3.0f;
            float fl = fminf(fmaxf(floorf(u), 0.f), 2.f);
            i0[k] = (int)fl;
            fr[k] = u - fl;
        }
        const float* tb = g_tex + (int)slist[jw] * 192;
#pragma unroll
        for (int a = 0; a < 2; a++)
#pragma unroll
            for (int bb = 0; bb < 2; bb++)
#pragma unroll
                for (int cc = 0; cc < 2; cc++) {
                    float wc = (a  ? fr[0] : 1.f - fr[0])
                             * (bb ? fr[1] : 1.f - fr[1])
                             * (cc ? fr[2] : 1.f - fr[2]);
                    int idx = ((i0[0] + a) * 16 + (i0[1] + bb) * 4 + (i0[2] + cc)) * 3;
                    col0 += wc * __ldg(tb + idx + 0);
                    col1 += wc * __ldg(tb + idx + 1);
                    col2 += wc * __ldg(tb + idx + 2);
                }
    }

    int p = y * 256 + x;
    float d0 = col0 - ref[p];
    float d1 = col1 - ref[65536 + p];
    float d2 = col2 - ref[131072 + p];
    double sum = (double)d0 * d0 + (double)d1 * d1 + (double)d2 * d2;

#pragma unroll
    for (int o = 16; o; o >>= 1) sum += __shfl_down_sync(0xffffffffu, sum, o);
    if ((tid & 31) == 0) ss[tid >> 5] = sum;
    __syncthreads();
    if (tid == 0) {
        double t = 0.0;
        for (int i = 0; i < 8; i++) t += ss[i];
        g_partial[b] = t;
        __threadfence();
        unsigned old = atomicAdd(&g_rcount, 1u);
        sflag = (old == NTILE - 1);
    }
    __syncthreads();
    if (sflag) {                              // last block: fixed-order deterministic tree
        sred[tid] = g_partial[tid];
        __syncthreads();
        for (int o = NTILE / 2; o; o >>= 1) {
            if (tid < o) sred[tid] += sred[tid + o];
            __syncthreads();
        }
        if (tid == 0) out[0] = (float)sred[0];
    }
}

extern "C" void kernel_launch(void* const* d_in, const int* in_sizes, int n_in,
                              void* d_out, int out_size) {
    const float* verts = (const float*)d_in[0];   // (1,322,3)
    const int*   faces = (const int*)  d_in[1];   // (1,640,3)
    const float* tex   = (const float*)d_in[2];   // (1,640,4,4,4,3)
    const float* ref   = (const float*)d_in[3];   // (1,3,256,256)
    const float* angle = (const float*)d_in[4];   // (1,)

    k1_kernel<<<TANH_BLOCKS + BIN_BLOCKS, 256>>>(verts, faces, angle, tex);
    k2_kernel<<<NTILE, 256>>>(ref, (float*)d_out);
}

// round 3
// speedup vs baseline: 1.9818x; 1.0286x over previous
#include <cuda_runtime.h>

#define Fn 640
#define Vn 322
#define EPSf 1e-8f
#define HALF_BIGf 5e9f
#define FOCALf 3.73205080756887729f
#define NTILE 256            // 16x16 tiles of 16x16 pixels
#define NSEG 4               // co-blocks per tile (face-list split)
#define SEGMAX 160           // ceil(Fn / NSEG)
#define TANH_BLOCKS 480      // 480*256 = 122880 = 640*4*4*4*3 exactly
#define BIN_BLOCKS 32        // 8 tiles per block (warp per tile)
#define INIT_BLOCKS 256      // zbuf init: 256*256 = 65536 pixels

// -------- device-global scratch (no allocations allowed) --------
__device__ float4 g_F0[Fn];                 // w0x w0y w0c w1x
__device__ float4 g_F1[Fn];                 // w1y w1c w2x w2y
__device__ float4 g_F2[Fn];                 // w2c zx  zy  zc
__device__ float  g_tex[Fn * 192];          // tanh(textures)
__device__ unsigned short g_list[NTILE * Fn];
__device__ int    g_cnt[NTILE];
__device__ unsigned long long g_zbuf[65536];
__device__ int    g_tiledone[NTILE];
__device__ double g_partial[NTILE];
__device__ unsigned int g_rcount;

__device__ __forceinline__ unsigned long long init_key() {
    return ((unsigned long long)__float_as_uint(HALF_BIGf)) << 32;   // no-hit sentinel
}

// ==== K1: tanh (0..479) | prep&bin (480..511) | zbuf/counter init (512..767) ====
__global__ void __launch_bounds__(256) k1_kernel(const float* __restrict__ verts,
                                                 const int*   __restrict__ faces,
                                                 const float* __restrict__ angle,
                                                 const float* __restrict__ tex) {
    int b = blockIdx.x, tid = threadIdx.x;
    if (b < TANH_BLOCKS) {
        int i = b * 256 + tid;
        g_tex[i] = tanhf(tex[i]);
        return;
    }
    if (b >= TANH_BLOCKS + BIN_BLOCKS) {     // ---- init blocks ----
        int ib = b - (TANH_BLOCKS + BIN_BLOCKS);
        g_zbuf[ib * 256 + tid] = init_key();
        if (ib == 0) {
            g_tiledone[tid] = 0;
            if (tid == 0) g_rcount = 0u;
        }
        return;
    }
    // ---- prep (redundant per bin block; cheap) ----
    __shared__ float sx[Vn], sy[Vn], sd[Vn];
    __shared__ float4 sF0[Fn], sF1[Fn], sF2[Fn];
    float th = angle[0] * 6.28318530717958647692f;
    float c = cosf(th), s = sinf(th);
    for (int v = tid; v < Vn; v += 256) {
        float x = verts[3 * v], y = verts[3 * v + 1], z = verts[3 * v + 2];
        float xr = c * x + s * z;
        float zr = -s * x + c * z;
        float depth = 2.732f - zr;
        sx[v] = FOCALf * xr / depth;
        sy[v] = FOCALf * y / depth;
        sd[v] = depth;
    }
    __syncthreads();
    bool writer = (b == TANH_BLOCKS);
    for (int f = tid; f < Fn; f += 256) {
        int i0 = faces[3 * f], i1 = faces[3 * f + 1], i2 = faces[3 * f + 2];
        float ax = sx[i0], ay = sy[i0];
        float bx = sx[i1], by = sy[i1];
        float cx = sx[i2], cy = sy[i2];
        float area = (bx - ax) * (cy - ay) - (by - ay) * (cx - ax);
        bool valid = fabsf(area) > EPSf;            // NaN -> invalid, matches jnp
        float denom = valid ? area : 1.0f;
        float e0x = cx - bx, e0y = cy - by;
        float w0x = -e0y / denom, w0y = e0x / denom, w0c = (e0y * bx - e0x * by) / denom;
        float e1x = ax - cx, e1y = ay - cy;
        float w1x = -e1y / denom, w1y = e1x / denom, w1c = (e1y * cx - e1x * cy) / denom;
        if (!valid) { w0x = 0.f; w0y = 0.f; w0c = -1e30f; w1x = 0.f; w1y = 0.f; w1c = 0.f; }
        float w2x = -(w0x + w1x), w2y = -(w0y + w1y), w2c = 1.0f - w0c - w1c;
        float d0 = sd[i0], d1 = sd[i1], d2 = sd[i2];
        float e02 = d0 - d2, e12 = d1 - d2;
        float zx = w0x * e02 + w1x * e12;
        float zy = w0y * e02 + w1y * e12;
        float zc = d2 + w0c * e02 + w1c * e12;
        float4 F0 = make_float4(w0x, w0y, w0c, w1x);
        float4 F1 = make_float4(w1y, w1c, w2x, w2y);
        float4 F2 = make_float4(w2c, zx, zy, zc);
        sF0[f] = F0; sF1[f] = F1; sF2[f] = F2;
        if (writer) { g_F0[f] = F0; g_F1[f] = F1; g_F2[f] = F2; }
    }
    __syncthreads();

    // ---- binning: warp per tile, dilated-edge conservative cull ----
    int wid = tid >> 5, lane = tid & 31;
    int tile = (b - TANH_BLOCKS) * 8 + wid;
    int tx = tile & 15, ty = tile >> 4;
    float cxt = (float)(tx * 16 + 8) / 128.0f - 1.0f;
    float cyt = 1.0f - (float)(ty * 16 + 8) / 128.0f;
    const float hext = 7.5f / 128.0f;
    int cnt = 0;
    for (int base = 0; base < Fn; base += 32) {
        int f = base + lane;
        float4 F0 = sF0[f];
        float4 F1 = sF1[f];
        float4 F2 = sF2[f];
        float v0 = fmaf(F0.x, cxt, fmaf(F0.y, cyt, F0.z));
        float m0 = (fabsf(F0.x) + fabsf(F0.y)) * hext
                 + 1e-5f * (fabsf(F0.x) + fabsf(F0.y) + fabsf(F0.z));
        float v1 = fmaf(F0.w, cxt, fmaf(F1.x, cyt, F1.y));
        float m1 = (fabsf(F0.w) + fabsf(F1.x)) * hext
                 + 1e-5f * (fabsf(F0.w) + fabsf(F1.x) + fabsf(F1.y));
        float v2 = fmaf(F1.z, cxt, fmaf(F1.w, cyt, F2.x));
        float m2 = (fabsf(F1.z) + fabsf(F1.w)) * hext
                 + 1e-5f * (fabsf(F1.z) + fabsf(F1.w) + fabsf(F2.x));
        bool pass = (v0 + m0 >= 0.f) & (v1 + m1 >= 0.f) & (v2 + m2 >= 0.f);
        unsigned mask = __ballot_sync(0xffffffffu, pass);
        if (pass) {
            int off = cnt + __popc(mask & ((1u << lane) - 1u));
            g_list[tile * Fn + off] = (unsigned short)f;
        }
        cnt += __popc(mask);
    }
    if (lane == 0) g_cnt[tile] = cnt;
}

// ==== K2: 4 co-blocks per tile raster -> packed atomicMin zbuf;
//          last co-block shades + loss; last tile reduces ====
__global__ void __launch_bounds__(256) k2_kernel(const float* __restrict__ ref,
                                                 float* __restrict__ out) {
    __shared__ float4 sF0[SEGMAX], sF1[SEGMAX], sF2[SEGMAX];
    __shared__ unsigned short slist[SEGMAX];
    __shared__ double ss[8];
    __shared__ double sred[NTILE];
    __shared__ int sflag;
    int b = blockIdx.x, tid = threadIdx.x;
    int tile = b >> 2, seg = b & 3;

    int cnt = g_cnt[tile];
    int lo = (cnt * seg) / NSEG;
    int hi = (cnt * (seg + 1)) / NSEG;
    int n = hi - lo;
    if (tid < n) {
        int f = g_list[tile * Fn + lo + tid];
        slist[tid] = (unsigned short)f;
        sF0[tid] = g_F0[f];
        sF1[tid] = g_F1[f];
        sF2[tid] = g_F2[f];
    }
    __syncthreads();

    int x = (tile & 15) * 16 + (tid & 15);
    int y = (tile >> 4) * 16 + (tid >> 4);
    int p = y * 256 + x;
    float px = (x + 0.5f) / 128.0f - 1.0f;
    float py = 1.0f - (y + 0.5f) / 128.0f;

    float best = HALF_BIGf;                  // strict < keeps z==HALF_BIG out (== ref hit rule)
    int jw = -1;
#pragma unroll 4
    for (int j = 0; j < n; j++) {
        float4 F0 = sF0[j];
        float4 F1 = sF1[j];
        float4 F2 = sF2[j];
        float w0 = fmaf(F0.x, px, fmaf(F0.y, py, F0.z));
        float w1 = fmaf(F0.w, px, fmaf(F1.x, py, F1.y));
        float w2 = fmaf(F1.z, px, fmaf(F1.w, py, F2.x));
        float z  = fmaf(F2.y, px, fmaf(F2.z, py, F2.w));
        bool take = (w0 >= 0.f) & (w1 >= 0.f) & (w2 >= 0.f) & (z > EPSf) & (z < best);
        if (take) { best = z; jw = j; }
    }
    if (jw >= 0) {
        unsigned long long key =
            (((unsigned long long)__float_as_uint(best)) << 32) | (unsigned)slist[jw];
        atomicMin(&g_zbuf[p], key);
    }
    __threadfence();                         // release this thread's zbuf update
    __syncthreads();
    if (tid == 0) {
        int old = atomicAdd(&g_tiledone[tile], 1);
        sflag = (old == NSEG - 1);           // last co-block runs the epilogue
    }
    __syncthreads();
    if (!sflag) return;

    // ---- epilogue: shade + loss for this tile ----
    unsigned long long key = __ldcg(&g_zbuf[p]);
    float col0 = 0.f, col1 = 0.f, col2 = 0.f;
    if (key < init_key()) {                  // hit: z strictly < 0.5*BIG
        int f = (int)(unsigned)(key & 0xFFFFFFFFu);
        float4 F0 = __ldg(&g_F0[f]);
        float4 F1 = __ldg(&g_F1[f]);
        float w0 = fmaf(F0.x, px, fmaf(F0.y, py, F0.z));
        float w1 = fmaf(F0.w, px, fmaf(F1.x, py, F1.y));
        float pw[3] = { w0, w1, 1.0f - w0 - w1 };
        int   i0[3];
        float fr[3];
#pragma unroll
        for (int k = 0; k < 3; k++) {
            float u  = fminf(fmaxf(pw[k], 0.f), 1.f) * 3.0f;
            float fl = fminf(fmaxf(floorf(u), 0.f), 2.f);
            i0[k] = (int)fl;
            fr[k] = u - fl;
        }
        const float* tb = g_tex + f * 192;
#pragma unroll
        for (int a = 0; a < 2; a++)
#pragma unroll
            for (int bb = 0; bb < 2; bb++)
#pragma unroll
                for (int cc = 0; cc < 2; cc++) {
                    float wc = (a  ? fr[0] : 1.f - fr[0])
                             * (bb ? fr[1] : 1.f - fr[1])
                             * (cc ? fr[2] : 1.f - fr[2]);
                    int idx = ((i0[0] + a) * 16 + (i0[1] + bb) * 4 + (i0[2] + cc)) * 3;
                    col0 += wc * __ldg(tb + idx + 0);
                    col1 += wc * __ldg(tb + idx + 1);
                    col2 += wc * __ldg(tb + idx + 2);
                }
    }
    float d0 = col0 - ref[p];
    float d1 = col1 - ref[65536 + p];
    float d2 = col2 - ref[131072 + p];
    double sum = (double)d0 * d0 + (double)d1 * d1 + (double)d2 * d2;

#pragma unroll
    for (int o = 16; o; o >>= 1) sum += __shfl_down_sync(0xffffffffu, sum, o);
    if ((tid & 31) == 0) ss[tid >> 5] = sum;
    __syncthreads();
    if (tid == 0) {
        double t = 0.0;
        for (int i = 0; i < 8; i++) t += ss[i];
        g_partial[tile] = t;
        __threadfence();
        unsigned old = atomicAdd(&g_rcount, 1u);
        sflag = (old == NTILE - 1);
    }
    __syncthreads();
    if (sflag) {                              // very last block: fixed-order tree
        sred[tid] = __ldcg(&g_partial[tid]);
        __syncthreads();
        for (int o = NTILE / 2; o; o >>= 1) {
            if (tid < o) sred[tid] += sred[tid + o];
            __syncthreads();
        }
        if (tid == 0) out[0] = (float)sred[0];
    }
}

extern "C" void kernel_launch(void* const* d_in, const int* in_sizes, int n_in,
                              void* d_out, int out_size) {
    const float* verts = (const float*)d_in[0];   // (1,322,3)
    const int*   faces = (const int*)  d_in[1];   // (1,640,3)
    const float* tex   = (const float*)d_in[2];   // (1,640,4,4,4,3)
    const float* ref   = (const float*)d_in[3];   // (1,3,256,256)
    const float* angle = (const float*)d_in[4];   // (1,)

    k1_kernel<<<TANH_BLOCKS + BIN_BLOCKS + INIT_BLOCKS, 256>>>(verts, faces, angle, tex);
    k2_kernel<<<NTILE * NSEG, 256>>>(ref, (float*)d_out);
}

// round 4
// speedup vs baseline: 2.2986x; 1.1599x over previous
#include <cuda_runtime.h>

#define Fn 640
#define Vn 322
#define EPSf 1e-8f
#define HALF_BIGf 5e9f
#define FOCALf 3.73205080756887729f
#define NTILE 256            // 16x16 tiles of 16x16 pixels
#define NSEG 4               // co-blocks per tile (static face-id split)
#define SEGF 160             // faces per segment (640/4)

// -------- device-global scratch (zero-init at load; counters are monotonic,
//          g_seg/g_partial fully rewritten every replay -> graph-safe) --------
__device__ float4 g_seg[NSEG * 65536];      // {w0, w1, fid_bits, zbits}
__device__ int    g_tiledone[NTILE];        // monotonic, check (old & 3) == 3
__device__ double g_partial[NTILE];
__device__ unsigned int g_rcount;           // monotonic, check (old & 255) == 255

__global__ void __launch_bounds__(256) fused_kernel(const float* __restrict__ verts,
                                                    const int*   __restrict__ faces,
                                                    const float* __restrict__ tex,
                                                    const float* __restrict__ ref,
                                                    const float* __restrict__ angle,
                                                    float* __restrict__ out) {
    __shared__ float sx[Vn], sy[Vn], sd[Vn];
    __shared__ float4 cF0[SEGF], cF1[SEGF], cF2[SEGF];
    __shared__ unsigned short clist[SEGF];
    __shared__ int swcnt[5];
    __shared__ int sn;
    __shared__ double ss[8];
    __shared__ int sflag;

    int b = blockIdx.x, tid = threadIdx.x;
    int tile = b >> 2, seg = b & 3;
    int tx = tile & 15, ty = tile >> 4;

    // ---- vertex transform (all verts, redundant per block; cheap) ----
    float th = angle[0] * 6.28318530717958647692f;
    float c = cosf(th), s = sinf(th);
    for (int v = tid; v < Vn; v += 256) {
        float x = verts[3 * v], y = verts[3 * v + 1], z = verts[3 * v + 2];
        float xr = c * x + s * z;
        float zr = -s * x + c * z;
        float depth = 2.732f - zr;
        sx[v] = FOCALf * xr / depth;
        sy[v] = FOCALf * y / depth;
        sd[v] = depth;
    }
    __syncthreads();

    // ---- plane compute + dilated-edge cull + compact (this seg's 160 faces) ----
    float cxt = (float)(tx * 16 + 8) / 128.0f - 1.0f;
    float cyt = 1.0f - (float)(ty * 16 + 8) / 128.0f;
    const float hext = 7.5f / 128.0f;

    bool pass = false;
    float4 F0, F1, F2;
    int f = seg * SEGF + tid;
    if (tid < SEGF) {
        int i0 = faces[3 * f], i1 = faces[3 * f + 1], i2 = faces[3 * f + 2];
        float ax = sx[i0], ay = sy[i0];
        float bx = sx[i1], by = sy[i1];
        float cx = sx[i2], cy = sy[i2];
        float area = (bx - ax) * (cy - ay) - (by - ay) * (cx - ax);
        bool valid = fabsf(area) > EPSf;            // NaN -> invalid, matches jnp
        float denom = valid ? area : 1.0f;
        float e0x = cx - bx, e0y = cy - by;
        float w0x = -e0y / denom, w0y = e0x / denom, w0c = (e0y * bx - e0x * by) / denom;
        float e1x = ax - cx, e1y = ay - cy;
        float w1x = -e1y / denom, w1y = e1x / denom, w1c = (e1y * cx - e1x * cy) / denom;
        if (!valid) { w0x = 0.f; w0y = 0.f; w0c = -1e30f; w1x = 0.f; w1y = 0.f; w1c = 0.f; }
        float w2x = -(w0x + w1x), w2y = -(w0y + w1y), w2c = 1.0f - w0c - w1c;
        float d0 = sd[i0], d1 = sd[i1], d2 = sd[i2];
        float e02 = d0 - d2, e12 = d1 - d2;
        float zx = w0x * e02 + w1x * e12;
        float zy = w0y * e02 + w1y * e12;
        float zc = d2 + w0c * e02 + w1c * e12;
        F0 = make_float4(w0x, w0y, w0c, w1x);
        F1 = make_float4(w1y, w1c, w2x, w2y);
        F2 = make_float4(w2c, zx, zy, zc);
        // conservative tile cull: max over pixel box of each edge plane >= -tol
        float v0 = fmaf(w0x, cxt, fmaf(w0y, cyt, w0c));
        float m0 = (fabsf(w0x) + fabsf(w0y)) * hext
                 + 1e-5f * (fabsf(w0x) + fabsf(w0y) + fabsf(w0c));
        float v1 = fmaf(w1x, cxt, fmaf(w1y, cyt, w1c));
        float m1 = (fabsf(w1x) + fabsf(w1y)) * hext
                 + 1e-5f * (fabsf(w1x) + fabsf(w1y) + fabsf(w1c));
        float v2 = fmaf(w2x, cxt, fmaf(w2y, cyt, w2c));
        float m2 = (fabsf(w2x) + fabsf(w2y)) * hext
                 + 1e-5f * (fabsf(w2x) + fabsf(w2y) + fabsf(w2c));
        pass = (v0 + m0 >= 0.f) & (v1 + m1 >= 0.f) & (v2 + m2 >= 0.f);
    }
    unsigned mask = __ballot_sync(0xffffffffu, pass);
    int w = tid >> 5, lane = tid & 31;
    if (lane == 0 && w < 5) swcnt[w] = __popc(mask);
    __syncthreads();
    if (pass) {
        int off = __popc(mask & ((1u << lane) - 1u));
        for (int i = 0; i < w; i++) off += swcnt[i];   // warp order = face order
        cF0[off] = F0; cF1[off] = F1; cF2[off] = F2;
        clist[off] = (unsigned short)f;
    }
    if (tid == 0) sn = swcnt[0] + swcnt[1] + swcnt[2] + swcnt[3] + swcnt[4];
    __syncthreads();
    int n = sn;

    // ---- raster: per-pixel min over this segment's culled faces ----
    int x = tx * 16 + (tid & 15);
    int y = ty * 16 + (tid >> 4);
    int p = y * 256 + x;
    float px = (x + 0.5f) / 128.0f - 1.0f;
    float py = 1.0f - (y + 0.5f) / 128.0f;

    float best = HALF_BIGf;                  // strict < == reference hit rule
    int jw = -1;
#pragma unroll 4
    for (int j = 0; j < n; j++) {
        float4 A  = cF0[j];
        float4 Bv = cF1[j];
        float4 Cv = cF2[j];
        float w0 = fmaf(A.x, px, fmaf(A.y, py, A.z));
        float w1 = fmaf(A.w, px, fmaf(Bv.x, py, Bv.y));
        float w2 = fmaf(Bv.z, px, fmaf(Bv.w, py, Cv.x));
        float z  = fmaf(Cv.y, px, fmaf(Cv.z, py, Cv.w));
        bool take = (w0 >= 0.f) & (w1 >= 0.f) & (w2 >= 0.f) & (z > EPSf) & (z < best);
        if (take) { best = z; jw = j; }      // ascending j == ascending f
    }
    float bw0 = 0.f, bw1 = 0.f;
    unsigned fid = 0;
    if (jw >= 0) {
        float4 A  = cF0[jw];
        float4 Bv = cF1[jw];
        bw0 = fmaf(A.x, px, fmaf(A.y, py, A.z));
        bw1 = fmaf(A.w, px, fmaf(Bv.x, py, Bv.y));
        fid = (unsigned)clist[jw];
    }
    g_seg[(seg << 16) + p] =
        make_float4(bw0, bw1, __uint_as_float(fid), __uint_as_float(__float_as_uint(best)));
    __threadfence();                         // release this thread's segment slot
    __syncthreads();
    if (tid == 0) {
        int old = atomicAdd(&g_tiledone[tile], 1);
        sflag = ((old & 3) == 3);            // last co-block of the tile (mod-4: replay-safe)
    }
    __syncthreads();
    if (!sflag) return;

    // ---- epilogue: merge 4 segments, shade (tanh on the fly), loss ----
    unsigned long long bk = 0xFFFFFFFFFFFFFFFFull;
    float w0 = 0.f, w1 = 0.f;
#pragma unroll
    for (int sg = 0; sg < NSEG; sg++) {
        float4 v = __ldcg(&g_seg[(sg << 16) + p]);
        unsigned long long k =
            (((unsigned long long)__float_as_uint(v.w)) << 32) | __float_as_uint(v.z);
        if (k < bk) { bk = k; w0 = v.x; w1 = v.y; }   // (z, fid) lexicographic min
    }
    float col0 = 0.f, col1 = 0.f, col2 = 0.f;
    if ((unsigned)(bk >> 32) < __float_as_uint(HALF_BIGf)) {
        int fw = (int)(unsigned)(bk & 0xFFFFFFFFu);
        float pw[3] = { w0, w1, 1.0f - w0 - w1 };
        int   i0[3];
        float fr[3];
#pragma unroll
        for (int k = 0; k < 3; k++) {
            float u  = fminf(fmaxf(pw[k], 0.f), 1.f) * 3.0f;
            float fl = fminf(fmaxf(floorf(u), 0.f), 2.f);
            i0[k] = (int)fl;
            fr[k] = u - fl;
        }
        const float* tb = tex + fw * 192;
#pragma unroll
        for (int a = 0; a < 2; a++)
#pragma unroll
            for (int bb = 0; bb < 2; bb++)
#pragma unroll
                for (int cc = 0; cc < 2; cc++) {
                    float wc = (a  ? fr[0] : 1.f - fr[0])
                             * (bb ? fr[1] : 1.f - fr[1])
                             * (cc ? fr[2] : 1.f - fr[2]);
                    int idx = ((i0[0] + a) * 16 + (i0[1] + bb) * 4 + (i0[2] + cc)) * 3;
                    col0 += wc * tanhf(__ldg(tb + idx + 0));
                    col1 += wc * tanhf(__ldg(tb + idx + 1));
                    col2 += wc * tanhf(__ldg(tb + idx + 2));
                }
    }
    float d0 = col0 - ref[p];
    float d1 = col1 - ref[65536 + p];
    float d2 = col2 - ref[131072 + p];
    double sum = (double)d0 * d0 + (double)d1 * d1 + (double)d2 * d2;

#pragma unroll
    for (int o = 16; o; o >>= 1) sum += __shfl_down_sync(0xffffffffu, sum, o);
    if (lane == 0) ss[w] = sum;
    __syncthreads();
    if (tid == 0) {
        double t = 0.0;
        for (int i = 0; i < 8; i++) t += ss[i];
        g_partial[tile] = t;
        __threadfence();
        unsigned old = atomicAdd(&g_rcount, 1u);
        sflag = ((old & 255) == 255);        // very last tile (mod-256: replay-safe)
    }
    __syncthreads();
    if (sflag) {                             // fixed-order deterministic final reduce
        double v = __ldcg(&g_partial[tid]);
#pragma unroll
        for (int o = 16; o; o >>= 1) v += __shfl_down_sync(0xffffffffu, v, o);
        if (lane == 0) ss[w] = v;
        __syncthreads();
        if (tid == 0) {
            double t = 0.0;
            for (int i = 0; i < 8; i++) t += ss[i];
            out[0] = (float)t;
        }
    }
}

extern "C" void kernel_launch(void* const* d_in, const int* in_sizes, int n_in,
                              void* d_out, int out_size) {
    const float* verts = (const float*)d_in[0];   // (1,322,3)
    const int*   faces = (const int*)  d_in[1];   // (1,640,3)
    const float* tex   = (const float*)d_in[2];   // (1,640,4,4,4,3)
    const float* ref   = (const float*)d_in[3];   // (1,3,256,256)
    const float* angle = (const float*)d_in[4];   // (1,)

    fused_kernel<<<NTILE * NSEG, 256>>>(verts, faces, tex, ref, angle, (float*)d_out);
}